// round 4
// baseline (speedup 1.0000x reference)
#include <cuda_runtime.h>
#include <cuda_fp16.h>

#define BB 256
#define SS 2048
#define EE 64
#define HH 128
#define G4 512   // 4*H

// x_proj scratch: [S][B][4H] fp32 = 1.07 GB
__device__ float g_xp[(size_t)SS * BB * G4];

__device__ __forceinline__ float sigm_f(float x) {
    return 1.0f / (1.0f + __expf(-x));
}
__device__ __forceinline__ float tanh_f(float x) {
    return 2.0f / (1.0f + __expf(-2.0f * x)) - 1.0f;
}

// ---- f32x2 packed-math helpers (sm_103a) ------------------------------------
typedef unsigned long long ull;

__device__ __forceinline__ ull fma2(ull a, ull b, ull c) {
    ull d;
    asm("fma.rn.f32x2 %0, %1, %2, %3;" : "=l"(d) : "l"(a), "l"(b), "l"(c));
    return d;
}
// bf16x2 (lo half = w_k, hi half = w_{k+1}) -> f32x2 (w_k, w_{k+1})
__device__ __forceinline__ ull bf2f2(unsigned int w) {
    unsigned int lo = w << 16;
    unsigned int hi = w & 0xFFFF0000u;
    ull r;
    asm("mov.b64 %0, {%1, %2};" : "=l"(r) : "r"(lo), "r"(hi));
    return r;
}
__device__ __forceinline__ float hsum2(ull v) {
    float x, y;
    asm("mov.b64 {%0, %1}, %2;" : "=f"(x), "=f"(y) : "l"(v));
    return x + y;
}
__device__ __forceinline__ unsigned int f2bf2(float hi, float lo) {
    unsigned int r;
    asm("cvt.rn.satfinite.bf16x2.f32 %0, %1, %2;" : "=r"(r) : "f"(hi), "f"(lo));
    return r;
}
__device__ __forceinline__ ull dup2(float x) {
    ull r;
    asm("mov.b64 %0, {%1, %1};" : "=l"(r) : "f"(x));
    return r;
}

// ---------------------------------------------------------------------------
// Kernel 1: x_proj[s][b][f] = dot(inputs[b][s][:], U_all[f][:]) + b_u[f]
// ---------------------------------------------------------------------------
__global__ __launch_bounds__(256) void xproj_kernel(
    const float* __restrict__ inputs,   // [B][S][E]
    const float* __restrict__ U_all,    // [4H][E]
    const float* __restrict__ b_u)      // [4H]
{
    __shared__ float xT[64 * 68];  // [e][b]
    __shared__ float uT[64 * 68];  // [e][f]

    const int s      = blockIdx.z;
    const int b_base = blockIdx.y * 64;
    const int f_base = blockIdx.x * 64;
    const int tid    = threadIdx.x;
    const int e      = tid & 63;
    const int r0     = tid >> 6;

    #pragma unroll
    for (int i = 0; i < 16; i++) {
        int r = r0 + i * 4;
        xT[e * 68 + r] = inputs[((size_t)(b_base + r) * SS + s) * EE + e];
        uT[e * 68 + r] = U_all[(size_t)(f_base + r) * EE + e];
    }
    __syncthreads();

    const int bi = (tid >> 4) * 4;
    const int fi = (tid & 15) * 4;

    ull acc[4][2];
    #pragma unroll
    for (int i = 0; i < 4; i++) { acc[i][0] = 0ULL; acc[i][1] = 0ULL; }

    #pragma unroll 16
    for (int k = 0; k < 64; k++) {
        float4 xv = *reinterpret_cast<const float4*>(&xT[k * 68 + bi]);
        ulonglong2 uvp = *reinterpret_cast<const ulonglong2*>(&uT[k * 68 + fi]);
        float xa[4] = {xv.x, xv.y, xv.z, xv.w};
        #pragma unroll
        for (int i = 0; i < 4; i++) {
            ull xx = dup2(xa[i]);
            acc[i][0] = fma2(xx, uvp.x, acc[i][0]);
            acc[i][1] = fma2(xx, uvp.y, acc[i][1]);
        }
    }

    float4 bu = *reinterpret_cast<const float4*>(&b_u[f_base + fi]);
    #pragma unroll
    for (int i = 0; i < 4; i++) {
        size_t o = ((size_t)s * BB + (size_t)(b_base + bi + i)) * G4 + f_base + fi;
        float a0, a1, a2, a3;
        asm("mov.b64 {%0, %1}, %2;" : "=f"(a0), "=f"(a1) : "l"(acc[i][0]));
        asm("mov.b64 {%0, %1}, %2;" : "=f"(a2), "=f"(a3) : "l"(acc[i][1]));
        float4 v;
        v.x = a0 + bu.x;
        v.y = a1 + bu.y;
        v.z = a2 + bu.z;
        v.w = a3 + bu.w;
        *reinterpret_cast<float4*>(&g_xp[o]) = v;
    }
}

// ---------------------------------------------------------------------------
// Kernel 2: scan. 128 CTAs x 512 threads, 2 batch rows per CTA.
// All SMEM traffic vectorized to 128-bit, conflict-free:
//   wg2 : uint4[r=64][c=128] ; uint4 = {g0,g1,g2,g3} bf16x2 at k-pair r, col c
//   wd2 : per-thread 16 words (4 uint4), record stride 20 words (bank-clean)
//   preg record: per (m,c) 20 floats = 16 gate partials (kq,g) + 4 cpart(kq)
// ---------------------------------------------------------------------------
#define SM_WG     0                      // 64*512 words  = 131072 B
#define SM_WD     131072                 // 512*20 words  =  40960 B
#define SM_H      172032                 // 2*128 floats  =   1024 B
#define SM_C      173056                 // 2*128 floats  =   1024 B
#define SM_PREC   174080                 // 2*128*20 f    =  20480 B
#define SM_RED    194560                 // 256 floats    =   1024 B
#define SMEM_BYTES 195584

__global__ __launch_bounds__(512, 1) void scan_kernel(
    const float* __restrict__ TI,      // [B][S]
    const float* __restrict__ W_all,   // [4H][H]
    const float* __restrict__ b_all,   // [4H]
    const float* __restrict__ W_d,     // [H][H]
    const float* __restrict__ b_d,     // [H]
    const float* __restrict__ W_out,   // [1][H]
    const float* __restrict__ b_out,   // [1]
    float* __restrict__ out)           // [B]
{
    extern __shared__ char smem[];
    unsigned int* wg2 = reinterpret_cast<unsigned int*>(smem + SM_WG);
    unsigned int* wd2 = reinterpret_cast<unsigned int*>(smem + SM_WD);
    float* hb   = reinterpret_cast<float*>(smem + SM_H);     // [2][128]
    float* cb   = reinterpret_cast<float*>(smem + SM_C);     // [2][128]
    float* prec = reinterpret_cast<float*>(smem + SM_PREC);  // [(m*128+c)*20 + slot]
    float* red  = reinterpret_cast<float*>(smem + SM_RED);

    const int t  = threadIdx.x;
    const int b0 = blockIdx.x * 2;
    const int c  = t & 127;
    const int kq = t >> 7;      // 0..3

    // ---- one-time packing ----
    // wg2[r*512 + c*4 + g] = bf16x2( W_all[g*128+c][2r], W_all[g*128+c][2r+1] )
    for (int u = t; u < 64 * 512; u += 512) {
        int r = u >> 9, rem = u & 511;
        int cc = rem >> 2, gg = rem & 3;
        float2 wv = *reinterpret_cast<const float2*>(&W_all[(size_t)(gg * 128 + cc) * HH + 2 * r]);
        wg2[u] = f2bf2(wv.y, wv.x);
    }
    // wd2[(kq*128+c)*20 + p] = bf16x2( W_d[c][kq*32+2p], W_d[c][kq*32+2p+1] ), p=0..15
    for (int u = t; u < 512 * 16; u += 512) {
        int p = u & 15, cc = (u >> 4) & 127, kqq = u >> 11;
        float2 wv = *reinterpret_cast<const float2*>(&W_d[(size_t)cc * HH + kqq * 32 + 2 * p]);
        wd2[(kqq * 128 + cc) * 20 + p] = f2bf2(wv.y, wv.x);
    }
    if (t < 256) { hb[t] = 0.0f; cb[t] = 0.0f; }

    // per-thread constants for phase B (threads 0..255: m = t>>7, j = c)
    float ba_r[4], bd_r = 0.0f, wout_r = 0.0f;
    if (t < 256) {
        #pragma unroll
        for (int g = 0; g < 4; g++) ba_r[g] = b_all[g * 128 + c];
        bd_r = b_d[c];
        wout_r = W_out[c];
    }
    const float bo = b_out[0];

    __syncthreads();

    const uint4* wgt4 = reinterpret_cast<const uint4*>(wg2) + kq * 16 * 128 + c;
    const uint4* wdt4 = reinterpret_cast<const uint4*>(wd2 + (kq * 128 + c) * 20);
    const ulonglong2* h0v = reinterpret_cast<const ulonglong2*>(hb + kq * 32);
    const ulonglong2* h1v = reinterpret_cast<const ulonglong2*>(hb + 128 + kq * 32);
    const ulonglong2* c0v = reinterpret_cast<const ulonglong2*>(cb + kq * 32);
    const ulonglong2* c1v = reinterpret_cast<const ulonglong2*>(cb + 128 + kq * 32);

    float* rec0 = prec + (size_t)c * 20;          // (m=0, c)
    float* rec1 = prec + (size_t)(128 + c) * 20;  // (m=1, c)

    float out_acc = 0.0f;

    for (int s = 0; s < SS; s++) {
        // prefetch phase-B globals early
        float xpv[4], ti = 0.0f;
        if (t < 256) {
            const int m = t >> 7;
            size_t xb = ((size_t)s * BB + b0 + m) * G4 + c;
            #pragma unroll
            for (int g = 0; g < 4; g++) xpv[g] = g_xp[xb + g * 128];
            ti = TI[(size_t)(b0 + m) * SS + s];
        }

        // wd weights: 4 x LDS.128
        uint4 wdv[4];
        #pragma unroll
        for (int q = 0; q < 4; q++) wdv[q] = wdt4[q];
        const unsigned int* wdw = reinterpret_cast<const unsigned int*>(wdv);

        // ---- Phase A: quarter-k partial dots ----
        ull acc0[4] = {0ULL, 0ULL, 0ULL, 0ULL};
        ull acc1[4] = {0ULL, 0ULL, 0ULL, 0ULL};
        ull d0 = 0ULL, d1 = 0ULL;

        #pragma unroll
        for (int p2 = 0; p2 < 8; p2++) {
            uint4 wv0 = wgt4[(2 * p2) * 128];       // gates, k-pair 2*p2
            uint4 wv1 = wgt4[(2 * p2 + 1) * 128];   // gates, k-pair 2*p2+1
            ulonglong2 hh0 = h0v[p2];
            ulonglong2 hh1 = h1v[p2];
            const unsigned int* w0 = reinterpret_cast<const unsigned int*>(&wv0);
            const unsigned int* w1 = reinterpret_cast<const unsigned int*>(&wv1);
            #pragma unroll
            for (int g = 0; g < 4; g++) {
                ull wA = bf2f2(w0[g]);
                ull wB = bf2f2(w1[g]);
                acc0[g] = fma2(hh0.x, wA, acc0[g]);
                acc0[g] = fma2(hh0.y, wB, acc0[g]);
                acc1[g] = fma2(hh1.x, wA, acc1[g]);
                acc1[g] = fma2(hh1.y, wB, acc1[g]);
            }
            ulonglong2 cc0 = c0v[p2];
            ulonglong2 cc1 = c1v[p2];
            ull dA = bf2f2(wdw[2 * p2]);
            ull dB = bf2f2(wdw[2 * p2 + 1]);
            d0 = fma2(cc0.x, dA, d0);
            d0 = fma2(cc0.y, dB, d0);
            d1 = fma2(cc1.x, dA, d1);
            d1 = fma2(cc1.y, dB, d1);
        }

        // write partial record: STS.128 per row + STS.32 cpart
        {
            float4 v0, v1;
            v0.x = hsum2(acc0[0]); v0.y = hsum2(acc0[1]);
            v0.z = hsum2(acc0[2]); v0.w = hsum2(acc0[3]);
            v1.x = hsum2(acc1[0]); v1.y = hsum2(acc1[1]);
            v1.z = hsum2(acc1[2]); v1.w = hsum2(acc1[3]);
            *reinterpret_cast<float4*>(rec0 + kq * 4) = v0;
            *reinterpret_cast<float4*>(rec1 + kq * 4) = v1;
            rec0[16 + kq] = hsum2(d0);
            rec1[16 + kq] = hsum2(d1);
        }
        __syncthreads();

        // ---- Phase B: gating (threads 0..255; (m, c)) ----
        if (t < 256) {
            const int m = t >> 7;
            const float* rc = prec + (size_t)t * 20;   // t = m*128 + c
            float4 r0 = *reinterpret_cast<const float4*>(rc);
            float4 r1 = *reinterpret_cast<const float4*>(rc + 4);
            float4 r2 = *reinterpret_cast<const float4*>(rc + 8);
            float4 r3 = *reinterpret_cast<const float4*>(rc + 12);
            float4 r4 = *reinterpret_cast<const float4*>(rc + 16);

            float fg = sigm_f((r0.x + r1.x) + (r2.x + r3.x) + ba_r[0] + xpv[0]);
            float ig = sigm_f((r0.y + r1.y) + (r2.y + r3.y) + ba_r[1] + xpv[1]);
            float og = sigm_f((r0.z + r1.z) + (r2.z + r3.z) + ba_r[2] + xpv[2]);
            float ct = sigm_f((r0.w + r1.w) + (r2.w + r3.w) + ba_r[3] + xpv[3]);
            float cp = (r4.x + r4.y) + (r4.z + r4.w) + bd_r;

            float cs1  = tanh_f(cp);
            float cold = cb[m * 128 + c];
            float cadj = (cold - cs1) + cs1 * ti;
            float cnew = fg * cadj + ig * ct;
            float hnew = og * tanh_f(cnew);
            cb[m * 128 + c] = cnew;
            hb[m * 128 + c] = hnew;
            out_acc += hnew * wout_r;
        }
        __syncthreads();
    }

    // ---- out[b] = sum_s h_s @ W_out + S * b_out ----
    if (t < 256) red[t] = out_acc;
    __syncthreads();
    if (t == 0) {
        float s0 = 0.0f;
        for (int k = 0; k < 128; k++) s0 += red[k];
        out[b0] = s0 + (float)SS * bo;
    }
    if (t == 1) {
        float s1 = 0.0f;
        for (int k = 0; k < 128; k++) s1 += red[128 + k];
        out[b0 + 1] = s1 + (float)SS * bo;
    }
}

// ---------------------------------------------------------------------------
extern "C" void kernel_launch(void* const* d_in, const int* in_sizes, int n_in,
                              void* d_out, int out_size)
{
    const float* inputs = (const float*)d_in[0];
    const float* TI     = (const float*)d_in[1];
    const float* W_all  = (const float*)d_in[2];
    const float* b_all  = (const float*)d_in[3];
    const float* U_all  = (const float*)d_in[4];
    const float* b_u    = (const float*)d_in[5];
    const float* W_d    = (const float*)d_in[6];
    const float* b_d    = (const float*)d_in[7];
    const float* W_out  = (const float*)d_in[8];
    const float* b_out  = (const float*)d_in[9];
    float* out = (float*)d_out;

    xproj_kernel<<<dim3(8, 4, SS), 256>>>(inputs, U_all, b_u);

    cudaFuncSetAttribute(scan_kernel,
                         cudaFuncAttributeMaxDynamicSharedMemorySize, SMEM_BYTES);
    scan_kernel<<<128, 512, SMEM_BYTES>>>(TI, W_all, b_all, W_d, b_d,
                                          W_out, b_out, out);
}